// round 3
// baseline (speedup 1.0000x reference)
#include <cuda_runtime.h>

#define N_CLASSES 2
#define N_FEATURES 100
#define DIM 10

// Scratch for the precomputed bilinear form Re(M)[k,a]  (2 x 100 floats).
__device__ float g_Mr[N_CLASSES * N_FEATURES];

// Kernel 1: Mr[k,a] = sum_{i,j} ( A_re[k,i,j,a]*wr_ij - A_im[k,i,j,a]*wi_ij )
// with wr_ij = pr_i*pr_j + pi_i*pi_j,  wi_ij = pr_i*pi_j - pi_i*pr_j.
// A layout: A[k,i,j,a] row-major => offset (k*100 + (i*10+j))*100 + a.
__global__ void compute_M_kernel(const float* __restrict__ A_re,
                                 const float* __restrict__ A_im,
                                 const float* __restrict__ psi_re,
                                 const float* __restrict__ psi_im) {
    __shared__ float wr[DIM * DIM];
    __shared__ float wi[DIM * DIM];
    int tid = threadIdx.x;
    if (tid < DIM * DIM) {
        int i = tid / DIM, j = tid % DIM;
        float pri = psi_re[i], pii = psi_im[i];
        float prj = psi_re[j], pij = psi_im[j];
        wr[tid] = pri * prj + pii * pij;
        wi[tid] = pri * pij - pii * prj;
    }
    __syncthreads();

    for (int idx = tid; idx < N_CLASSES * N_FEATURES; idx += blockDim.x) {
        int k = idx / N_FEATURES;
        int a = idx % N_FEATURES;
        float sum = 0.0f;
        const float* are = A_re + (size_t)k * DIM * DIM * N_FEATURES + a;
        const float* aim = A_im + (size_t)k * DIM * DIM * N_FEATURES + a;
        #pragma unroll
        for (int m = 0; m < DIM * DIM; m++) {
            sum += are[m * N_FEATURES] * wr[m] - aim[m * N_FEATURES] * wi[m];
        }
        g_Mr[idx] = sum;
    }
}

// Kernel 2: out[t] = ( x[t,:] . Mr[0,:], x[t,:] . Mr[1,:] )
// One thread per row. 25 float4 loads per row (400 B, 16B-aligned for all t).
__global__ __launch_bounds__(256) void gemv_kernel(const float* __restrict__ x,
                                                   float2* __restrict__ out) {
    __shared__ float4 m0[N_FEATURES / 4];
    __shared__ float4 m1[N_FEATURES / 4];
    int tid = threadIdx.x;
    if (tid < N_FEATURES / 4) {
        m0[tid] = reinterpret_cast<const float4*>(g_Mr)[tid];
        m1[tid] = reinterpret_cast<const float4*>(g_Mr + N_FEATURES)[tid];
    }
    __syncthreads();

    int t = blockIdx.x * blockDim.x + tid;
    const float4* xr = reinterpret_cast<const float4*>(x + (size_t)t * N_FEATURES);

    float acc0 = 0.0f, acc1 = 0.0f;
    #pragma unroll
    for (int i = 0; i < N_FEATURES / 4; i++) {
        float4 xv = xr[i];
        float4 a = m0[i];
        float4 b = m1[i];
        acc0 += xv.x * a.x + xv.y * a.y + xv.z * a.z + xv.w * a.w;
        acc1 += xv.x * b.x + xv.y * b.y + xv.z * b.z + xv.w * b.w;
    }
    out[t] = make_float2(acc0, acc1);
}

extern "C" void kernel_launch(void* const* d_in, const int* in_sizes, int n_in,
                              void* d_out, int out_size) {
    const float* x      = (const float*)d_in[0];
    const float* A_re   = (const float*)d_in[1];
    const float* A_im   = (const float*)d_in[2];
    const float* psi_re = (const float*)d_in[3];
    const float* psi_im = (const float*)d_in[4];
    float2* out = (float2*)d_out;

    int T = in_sizes[0] / N_FEATURES;   // 262144

    compute_M_kernel<<<1, 256>>>(A_re, A_im, psi_re, psi_im);

    int block = 256;
    int grid = (T + block - 1) / block;
    gemv_kernel<<<grid, block>>>(x, out);
}

// round 4
// speedup vs baseline: 1.0609x; 1.0609x over previous
#include <cuda_runtime.h>

#define N_CLASSES 2
#define N_FEATURES 100
#define DIM 10

// Precomputed bilinear form Re(M)[k,a]  (2 x 100 floats).
__device__ float g_Mr[N_CLASSES * N_FEATURES];

// Kernel 1: one block per output element (k,a), 200 blocks.
// Mr[k,a] = sum_m ( A_re[k,m,a]*wr[m] - A_im[k,m,a]*wi[m] ),  m = i*10+j
__global__ void compute_M_kernel(const float* __restrict__ A_re,
                                 const float* __restrict__ A_im,
                                 const float* __restrict__ psi_re,
                                 const float* __restrict__ psi_im) {
    const int k = blockIdx.x / N_FEATURES;
    const int a = blockIdx.x % N_FEATURES;
    const int tid = threadIdx.x;          // 128 threads

    __shared__ float warp_sum[4];

    float s = 0.0f;
    if (tid < DIM * DIM) {
        int i = tid / DIM, j = tid % DIM;
        float pri = psi_re[i], pii = psi_im[i];
        float prj = psi_re[j], pij = psi_im[j];
        float wr = pri * prj + pii * pij;
        float wi = pri * pij - pii * prj;
        size_t off = ((size_t)k * DIM * DIM + tid) * N_FEATURES + a;
        s = A_re[off] * wr - A_im[off] * wi;
    }
    // warp reduce
    #pragma unroll
    for (int o = 16; o > 0; o >>= 1) s += __shfl_xor_sync(0xFFFFFFFF, s, o);
    if ((tid & 31) == 0) warp_sum[tid >> 5] = s;
    __syncthreads();
    if (tid == 0)
        g_Mr[blockIdx.x] = warp_sum[0] + warp_sum[1] + warp_sum[2] + warp_sum[3];
}

// Kernel 2: warp per row. Lane l (<25) loads float4 chunk l of the row
// (400 B contiguous per warp -> ~4 L1 wavefronts), dots against per-lane
// register copies of M, butterfly-reduces, lane 0 stores float2.
__global__ __launch_bounds__(256) void gemv_kernel(const float* __restrict__ x,
                                                   float2* __restrict__ out,
                                                   int T) {
    const int lane = threadIdx.x & 31;
    const int warp = (blockIdx.x * blockDim.x + threadIdx.x) >> 5;
    const int nwarps = (gridDim.x * blockDim.x) >> 5;

    // Per-lane M coefficients (zero for lanes 25..31).
    float4 ma = make_float4(0.f, 0.f, 0.f, 0.f);
    float4 mb = ma;
    if (lane < N_FEATURES / 4) {
        ma = reinterpret_cast<const float4*>(g_Mr)[lane];
        mb = reinterpret_cast<const float4*>(g_Mr + N_FEATURES)[lane];
    }

    const bool active = (lane < N_FEATURES / 4);

    // 4-row unroll for MLP.
    int r = warp * 4;
    const int rstride = nwarps * 4;
    for (; r + 3 < T; r += rstride) {
        float4 xv0 = make_float4(0.f,0.f,0.f,0.f), xv1 = xv0, xv2 = xv0, xv3 = xv0;
        if (active) {
            xv0 = reinterpret_cast<const float4*>(x + (size_t)(r + 0) * N_FEATURES)[lane];
            xv1 = reinterpret_cast<const float4*>(x + (size_t)(r + 1) * N_FEATURES)[lane];
            xv2 = reinterpret_cast<const float4*>(x + (size_t)(r + 2) * N_FEATURES)[lane];
            xv3 = reinterpret_cast<const float4*>(x + (size_t)(r + 3) * N_FEATURES)[lane];
        }
        float a0 = xv0.x*ma.x + xv0.y*ma.y + xv0.z*ma.z + xv0.w*ma.w;
        float b0 = xv0.x*mb.x + xv0.y*mb.y + xv0.z*mb.z + xv0.w*mb.w;
        float a1 = xv1.x*ma.x + xv1.y*ma.y + xv1.z*ma.z + xv1.w*ma.w;
        float b1 = xv1.x*mb.x + xv1.y*mb.y + xv1.z*mb.z + xv1.w*mb.w;
        float a2 = xv2.x*ma.x + xv2.y*ma.y + xv2.z*ma.z + xv2.w*ma.w;
        float b2 = xv2.x*mb.x + xv2.y*mb.y + xv2.z*mb.z + xv2.w*mb.w;
        float a3 = xv3.x*ma.x + xv3.y*ma.y + xv3.z*ma.z + xv3.w*ma.w;
        float b3 = xv3.x*mb.x + xv3.y*mb.y + xv3.z*mb.z + xv3.w*mb.w;
        #pragma unroll
        for (int o = 16; o > 0; o >>= 1) {
            a0 += __shfl_xor_sync(0xFFFFFFFF, a0, o);
            b0 += __shfl_xor_sync(0xFFFFFFFF, b0, o);
            a1 += __shfl_xor_sync(0xFFFFFFFF, a1, o);
            b1 += __shfl_xor_sync(0xFFFFFFFF, b1, o);
            a2 += __shfl_xor_sync(0xFFFFFFFF, a2, o);
            b2 += __shfl_xor_sync(0xFFFFFFFF, b2, o);
            a3 += __shfl_xor_sync(0xFFFFFFFF, a3, o);
            b3 += __shfl_xor_sync(0xFFFFFFFF, b3, o);
        }
        if (lane == 0) {
            out[r + 0] = make_float2(a0, b0);
            out[r + 1] = make_float2(a1, b1);
            out[r + 2] = make_float2(a2, b2);
            out[r + 3] = make_float2(a3, b3);
        }
    }
    // Tail (T divisible by 4 in practice, but be safe).
    for (; r < T; r++) {
        float4 xv = make_float4(0.f,0.f,0.f,0.f);
        if (active)
            xv = reinterpret_cast<const float4*>(x + (size_t)r * N_FEATURES)[lane];
        float a0 = xv.x*ma.x + xv.y*ma.y + xv.z*ma.z + xv.w*ma.w;
        float b0 = xv.x*mb.x + xv.y*mb.y + xv.z*mb.z + xv.w*mb.w;
        #pragma unroll
        for (int o = 16; o > 0; o >>= 1) {
            a0 += __shfl_xor_sync(0xFFFFFFFF, a0, o);
            b0 += __shfl_xor_sync(0xFFFFFFFF, b0, o);
        }
        if (lane == 0) out[r] = make_float2(a0, b0);
    }
}

extern "C" void kernel_launch(void* const* d_in, const int* in_sizes, int n_in,
                              void* d_out, int out_size) {
    const float* x      = (const float*)d_in[0];
    const float* A_re   = (const float*)d_in[1];
    const float* A_im   = (const float*)d_in[2];
    const float* psi_re = (const float*)d_in[3];
    const float* psi_im = (const float*)d_in[4];
    float2* out = (float2*)d_out;

    int T = in_sizes[0] / N_FEATURES;   // 262144

    compute_M_kernel<<<N_CLASSES * N_FEATURES, 128>>>(A_re, A_im, psi_re, psi_im);

    // 8192 warps -> each warp handles 32 rows (8 unrolled groups).
    gemv_kernel<<<1024, 256>>>(x, out, T);
}

// round 8
// speedup vs baseline: 1.3574x; 1.2796x over previous
#include <cuda_runtime.h>
#include <cstdint>

#define N_CLASSES 2
#define N_FEATURES 100
#define DIM 10

#define BLOCK     128
#define TILE_ROWS 128
#define F4        25      // float4 chunks per row
#define STRIDE_F  108     // padded smem row stride (floats) -> conflict-free LDS.128

// Precomputed bilinear form Re(M)[k,a]  (2 x 100 floats).
__device__ float g_Mr[N_CLASSES * N_FEATURES];

// ---------------------------------------------------------------------------
// Kernel 1: one block per output element (k,a), 200 blocks.
// Mr[k,a] = sum_m ( A_re[k,m,a]*wr[m] - A_im[k,m,a]*wi[m] ),  m = i*10+j
__global__ void compute_M_kernel(const float* __restrict__ A_re,
                                 const float* __restrict__ A_im,
                                 const float* __restrict__ psi_re,
                                 const float* __restrict__ psi_im) {
    const int k = blockIdx.x / N_FEATURES;
    const int a = blockIdx.x % N_FEATURES;
    const int tid = threadIdx.x;          // 128 threads

    __shared__ float warp_sum[4];

    float s = 0.0f;
    if (tid < DIM * DIM) {
        int i = tid / DIM, j = tid % DIM;
        float pri = psi_re[i], pii = psi_im[i];
        float prj = psi_re[j], pij = psi_im[j];
        float wr = pri * prj + pii * pij;
        float wi = pri * pij - pii * prj;
        size_t off = ((size_t)k * DIM * DIM + tid) * N_FEATURES + a;
        s = A_re[off] * wr - A_im[off] * wi;
    }
    #pragma unroll
    for (int o = 16; o > 0; o >>= 1) s += __shfl_xor_sync(0xFFFFFFFF, s, o);
    if ((tid & 31) == 0) warp_sum[tid >> 5] = s;
    __syncthreads();
    if (tid == 0)
        g_Mr[blockIdx.x] = warp_sum[0] + warp_sum[1] + warp_sum[2] + warp_sum[3];
}

// ---------------------------------------------------------------------------
__device__ __forceinline__ void cp_async16(unsigned int dst_smem, const void* src) {
    asm volatile("cp.async.cg.shared.global [%0], [%1], 16;\n"
                 :: "r"(dst_smem), "l"(src));
}
__device__ __forceinline__ void cp_async_commit_wait_all() {
    asm volatile("cp.async.commit_group;\n");
    asm volatile("cp.async.wait_group 0;\n" ::: "memory");
}

// Kernel 2: one block per 128-row tile. cp.async-stage the tile (fully
// coalesced, 25-deep per thread), then thread t dots padded smem row t
// against M (smem broadcasts). No shuffles, no cross-thread reduction.
__global__ __launch_bounds__(BLOCK) void gemv_kernel(const float* __restrict__ x,
                                                     float2* __restrict__ out,
                                                     int T) {
    extern __shared__ float smem[];
    float* msh  = smem;                        // 2*N_FEATURES floats (800 B)
    float* tile = smem + 2 * N_FEATURES;       // TILE_ROWS * STRIDE_F floats

    const int tid = threadIdx.x;
    const int row0 = blockIdx.x * TILE_ROWS;

    // Stage M into smem (50 float4 chunks).
    if (tid < (2 * N_FEATURES) / 4) {
        reinterpret_cast<float4*>(msh)[tid] =
            reinterpret_cast<const float4*>(g_Mr)[tid];
    }

    // Async-load the tile: chunk c covers floats [c*4, c*4+4) of the
    // contiguous 128x100 region starting at row0.
    const float* gbase = x + (size_t)row0 * N_FEATURES;
    unsigned int tile_u32 = (unsigned int)__cvta_generic_to_shared(tile);
    const int max_chunks = ((T - row0) < TILE_ROWS ? (T - row0) : TILE_ROWS) * F4;
    #pragma unroll
    for (int k = 0; k < F4; k++) {
        int c = tid + k * BLOCK;               // 0..3199
        int r = c / F4;
        int col = c - r * F4;
        if (c < max_chunks)
            cp_async16(tile_u32 + (unsigned int)(r * STRIDE_F + col * 4) * 4,
                       gbase + (size_t)c * 4);
    }
    cp_async_commit_wait_all();
    __syncthreads();

    // Compute: thread t -> row t of the tile.
    int t = row0 + tid;
    if (t < T) {
        const float4* xr = reinterpret_cast<const float4*>(tile + tid * STRIDE_F);
        const float4* m0 = reinterpret_cast<const float4*>(msh);
        const float4* m1 = reinterpret_cast<const float4*>(msh + N_FEATURES);
        float a = 0.0f, b = 0.0f;
        #pragma unroll
        for (int i = 0; i < F4; i++) {
            float4 xv = xr[i];
            float4 u = m0[i];
            float4 v = m1[i];
            a += xv.x * u.x + xv.y * u.y + xv.z * u.z + xv.w * u.w;
            b += xv.x * v.x + xv.y * v.y + xv.z * v.z + xv.w * v.w;
        }
        out[t] = make_float2(a, b);
    }
}

// ---------------------------------------------------------------------------
extern "C" void kernel_launch(void* const* d_in, const int* in_sizes, int n_in,
                              void* d_out, int out_size) {
    const float* x      = (const float*)d_in[0];
    const float* A_re   = (const float*)d_in[1];
    const float* A_im   = (const float*)d_in[2];
    const float* psi_re = (const float*)d_in[3];
    const float* psi_im = (const float*)d_in[4];
    float2* out = (float2*)d_out;

    int T = in_sizes[0] / N_FEATURES;   // 262144

    compute_M_kernel<<<N_CLASSES * N_FEATURES, 128>>>(A_re, A_im, psi_re, psi_im);

    const int smem_bytes = (2 * N_FEATURES + TILE_ROWS * STRIDE_F) * sizeof(float); // 56096
    cudaFuncSetAttribute(gemv_kernel,
                         cudaFuncAttributeMaxDynamicSharedMemorySize, smem_bytes);

    int grid = (T + TILE_ROWS - 1) / TILE_ROWS;   // 2048
    gemv_kernel<<<grid, BLOCK, smem_bytes>>>(x, out, T);
}

// round 9
// speedup vs baseline: 1.4833x; 1.0927x over previous
#include <cuda_runtime.h>
#include <cstdint>

#define N_CLASSES 2
#define N_FEATURES 100
#define DIM 10

#define BLOCK     128
#define TILE_ROWS 128
#define F4        25      // float4 chunks per row
#define STRIDE_F  108     // padded smem row stride (floats) -> conflict-free LDS.128
#define TILE_F    (TILE_ROWS * STRIDE_F)
#define GRID      296     // 2 blocks per SM, one wave

// Precomputed bilinear form Re(M)[k,a]  (2 x 100 floats).
__device__ float g_Mr[N_CLASSES * N_FEATURES];

// ---------------------------------------------------------------------------
// Kernel 1: one block per output element (k,a), 200 blocks.
__global__ void compute_M_kernel(const float* __restrict__ A_re,
                                 const float* __restrict__ A_im,
                                 const float* __restrict__ psi_re,
                                 const float* __restrict__ psi_im) {
    const int k = blockIdx.x / N_FEATURES;
    const int a = blockIdx.x % N_FEATURES;
    const int tid = threadIdx.x;          // 128 threads

    __shared__ float warp_sum[4];

    float s = 0.0f;
    if (tid < DIM * DIM) {
        int i = tid / DIM, j = tid % DIM;
        float pri = psi_re[i], pii = psi_im[i];
        float prj = psi_re[j], pij = psi_im[j];
        float wr = pri * prj + pii * pij;
        float wi = pri * pij - pii * prj;
        size_t off = ((size_t)k * DIM * DIM + tid) * N_FEATURES + a;
        s = A_re[off] * wr - A_im[off] * wi;
    }
    #pragma unroll
    for (int o = 16; o > 0; o >>= 1) s += __shfl_xor_sync(0xFFFFFFFF, s, o);
    if ((tid & 31) == 0) warp_sum[tid >> 5] = s;
    __syncthreads();
    if (tid == 0)
        g_Mr[blockIdx.x] = warp_sum[0] + warp_sum[1] + warp_sum[2] + warp_sum[3];
}

// ---------------------------------------------------------------------------
__device__ __forceinline__ void cp_async16(unsigned int dst_smem, const void* src) {
    asm volatile("cp.async.cg.shared.global [%0], [%1], 16;\n"
                 :: "r"(dst_smem), "l"(src));
}
__device__ __forceinline__ void cp_async_commit() {
    asm volatile("cp.async.commit_group;\n");
}
template <int N>
__device__ __forceinline__ void cp_async_wait() {
    asm volatile("cp.async.wait_group %0;\n" :: "n"(N) : "memory");
}

// Issue the 25 cp.asyncs for one tile into the given smem buffer.
__device__ __forceinline__ void issue_tile_load(const float* __restrict__ x,
                                                int tile, unsigned int buf_u32,
                                                int tid) {
    const float* gbase = x + (size_t)tile * TILE_ROWS * N_FEATURES;
    #pragma unroll
    for (int k = 0; k < F4; k++) {
        int c = tid + k * BLOCK;               // 0..3199
        int r = c / F4;
        int col = c - r * F4;
        cp_async16(buf_u32 + (unsigned int)(r * STRIDE_F + col * 4) * 4,
                   gbase + (size_t)c * 4);
    }
    cp_async_commit();
}

// Kernel 2: persistent blocks (2/SM), double-buffered cp.async pipeline.
// While computing tile i from buffer b, tile i+stride streams into buffer b^1.
__global__ __launch_bounds__(BLOCK) void gemv_kernel(const float* __restrict__ x,
                                                     float2* __restrict__ out,
                                                     int ntiles) {
    extern __shared__ float smem[];
    float* msh = smem;                         // 2*N_FEATURES floats
    float* tiles[2] = { smem + 2 * N_FEATURES,
                        smem + 2 * N_FEATURES + TILE_F };

    const int tid = threadIdx.x;
    unsigned int buf_u32[2] = {
        (unsigned int)__cvta_generic_to_shared(tiles[0]),
        (unsigned int)__cvta_generic_to_shared(tiles[1]) };

    // Stage M into smem.
    if (tid < (2 * N_FEATURES) / 4) {
        reinterpret_cast<float4*>(msh)[tid] =
            reinterpret_cast<const float4*>(g_Mr)[tid];
    }

    const int stride = gridDim.x;
    int tile = blockIdx.x;
    if (tile >= ntiles) return;

    // Prologue: load first tile into buffer 0.
    issue_tile_load(x, tile, buf_u32[0], tid);

    int buf = 0;
    for (; tile < ntiles; tile += stride, buf ^= 1) {
        int next = tile + stride;
        if (next < ntiles) {
            issue_tile_load(x, next, buf_u32[buf ^ 1], tid);
            cp_async_wait<1>();   // wait for current tile only
        } else {
            cp_async_wait<0>();
        }
        __syncthreads();          // current tile fully visible to all threads

        // Compute: thread t -> row t of this tile.
        {
            const float4* xr = reinterpret_cast<const float4*>(tiles[buf] + tid * STRIDE_F);
            const float4* m0 = reinterpret_cast<const float4*>(msh);
            const float4* m1 = reinterpret_cast<const float4*>(msh + N_FEATURES);
            float a = 0.0f, b = 0.0f;
            #pragma unroll
            for (int i = 0; i < F4; i++) {
                float4 xv = xr[i];
                float4 u = m0[i];
                float4 v = m1[i];
                a += xv.x * u.x + xv.y * u.y + xv.z * u.z + xv.w * u.w;
                b += xv.x * v.x + xv.y * v.y + xv.z * v.z + xv.w * v.w;
            }
            out[tile * TILE_ROWS + tid] = make_float2(a, b);
        }
        __syncthreads();          // done reading buf before it is reloaded
    }
}

// ---------------------------------------------------------------------------
extern "C" void kernel_launch(void* const* d_in, const int* in_sizes, int n_in,
                              void* d_out, int out_size) {
    const float* x      = (const float*)d_in[0];
    const float* A_re   = (const float*)d_in[1];
    const float* A_im   = (const float*)d_in[2];
    const float* psi_re = (const float*)d_in[3];
    const float* psi_im = (const float*)d_in[4];
    float2* out = (float2*)d_out;

    int T = in_sizes[0] / N_FEATURES;   // 262144
    int ntiles = T / TILE_ROWS;         // 2048 (T is a multiple of 128)

    compute_M_kernel<<<N_CLASSES * N_FEATURES, 128>>>(A_re, A_im, psi_re, psi_im);

    const int smem_bytes = (2 * N_FEATURES + 2 * TILE_F) * sizeof(float); // 111392
    cudaFuncSetAttribute(gemv_kernel,
                         cudaFuncAttributeMaxDynamicSharedMemorySize, smem_bytes);

    gemv_kernel<<<GRID, BLOCK, smem_bytes>>>(x, out, ntiles);
}